// round 5
// baseline (speedup 1.0000x reference)
#include <cuda_runtime.h>
#include <math.h>

#define C_DIM    128000
#define C_VEC    (C_DIM / 4)         // 32000 float4 per row
#define B_ROWS   2048
#define SPLIT    25
#define CHUNK_V  (C_VEC / SPLIT)     // 1280 float4 per chunk
#define THREADS  256                 // 1280 / 256 = 5 iterations exactly
#define NITER    (CHUNK_V / THREADS)

// partial per (row, split): x=sum_exp, y=m1, z=m2, w=unused
__device__ float4 g_partial[B_ROWS * SPLIT];
// per-row arrival counter (zero-init at load; reset to 0 by the finishing
// block each call -> deterministic across graph replays)
__device__ unsigned int g_count[B_ROWS];

__device__ __forceinline__ void top2_val(float& m1, float& m2, float v) {
    float t  = fminf(m1, v);
    m1 = fmaxf(m1, v);
    m2 = fmaxf(m2, t);
}

__global__ __launch_bounds__(THREADS, 8)
void fused_kernel(const float* __restrict__ logits,
                  const int* __restrict__ y,
                  float* __restrict__ out) {
    const int unit  = blockIdx.x;            // 0 .. B_ROWS*SPLIT-1
    const int row   = unit / SPLIT;
    const int split = unit - row * SPLIT;

    const float4* __restrict__ p =
        reinterpret_cast<const float4*>(logits + (size_t)row * C_DIM)
        + split * CHUNK_V;

    const int tid = threadIdx.x;

    float sum = 0.0f;
    float m1 = -INFINITY, m2 = -INFINITY;

    #pragma unroll
    for (int it = 0; it < NITER; it++) {
        float4 v = __ldcs(p + it * THREADS + tid);
        sum += __expf(v.x);
        sum += __expf(v.y);
        sum += __expf(v.z);
        sum += __expf(v.w);
        top2_val(m1, m2, v.x);
        top2_val(m1, m2, v.y);
        top2_val(m1, m2, v.z);
        top2_val(m1, m2, v.w);
    }

    // ---- warp reduction ----
    const unsigned FULL = 0xFFFFFFFFu;
    #pragma unroll
    for (int off = 16; off > 0; off >>= 1) {
        sum += __shfl_xor_sync(FULL, sum, off);
        float om1 = __shfl_xor_sync(FULL, m1, off);
        float om2 = __shfl_xor_sync(FULL, m2, off);
        float nm1 = fmaxf(m1, om1);
        m2 = fmaxf(fminf(m1, om1), fmaxf(m2, om2));
        m1 = nm1;
    }

    // ---- cross-warp reduction ----
    __shared__ float s_sum[THREADS / 32];
    __shared__ float s_m1[THREADS / 32];
    __shared__ float s_m2[THREADS / 32];
    __shared__ unsigned int s_last;

    const int wid = tid >> 5;
    const int lid = tid & 31;
    if (lid == 0) { s_sum[wid] = sum; s_m1[wid] = m1; s_m2[wid] = m2; }
    __syncthreads();

    if (wid == 0) {
        const int nw = THREADS / 32;
        float fsum = (lid < nw) ? s_sum[lid] : 0.0f;
        float fm1  = (lid < nw) ? s_m1[lid]  : -INFINITY;
        float fm2  = (lid < nw) ? s_m2[lid]  : -INFINITY;

        #pragma unroll
        for (int off = nw / 2; off > 0; off >>= 1) {
            fsum += __shfl_xor_sync(FULL, fsum, off);
            float om1 = __shfl_xor_sync(FULL, fm1, off);
            float om2 = __shfl_xor_sync(FULL, fm2, off);
            float nm1 = fmaxf(fm1, om1);
            fm2 = fmaxf(fminf(fm1, om1), fmaxf(fm2, om2));
            fm1 = nm1;
        }

        if (lid == 0) {
            // publish this chunk's partial
            g_partial[unit] = make_float4(fsum, fm1, fm2, 0.0f);
            __threadfence();
            // signal arrival; last arriver finalizes the row
            unsigned int prev = atomicAdd(&g_count[row], 1u);
            s_last = (prev == SPLIT - 1) ? 1u : 0u;
        }
    }
    __syncthreads();

    // ---- finalize: last-arriving block for this row, done by warp 0 ----
    if (s_last && wid == 0) {
        float tsum = 0.0f;
        float tm1 = -INFINITY, tm2 = -INFINITY;
        if (lid < SPLIT) {
            float4 v = g_partial[row * SPLIT + lid];
            tsum = v.x; tm1 = v.y; tm2 = v.z;
        }
        #pragma unroll
        for (int off = 16; off > 0; off >>= 1) {
            tsum += __shfl_xor_sync(FULL, tsum, off);
            float om1 = __shfl_xor_sync(FULL, tm1, off);
            float om2 = __shfl_xor_sync(FULL, tm2, off);
            float nm1 = fmaxf(tm1, om1);
            tm2 = fmaxf(fminf(tm1, om1), fmaxf(tm2, om2));
            tm1 = nm1;
        }

        if (lid == 0) {
            int yv = y[row];
            if (yv < 0)      yv = 0;
            if (yv >= C_DIM) yv = C_DIM - 1;
            const float vy = logits[(size_t)row * C_DIM + (size_t)yv];

            // y is argmax  <=>  logits[row][y] == global max (distinct values)
            const float first = (vy == tm1) ? tm2 : tm1;
            out[row] = first - logf(tsum - first);

            // reset counter for the next (graph-replayed) call
            g_count[row] = 0u;
        }
    }
}

extern "C" void kernel_launch(void* const* d_in, const int* in_sizes, int n_in,
                              void* d_out, int out_size) {
    const float* logits = (const float*)d_in[0];
    const int*   y      = (const int*)d_in[1];
    float*       out    = (float*)d_out;
    (void)in_sizes; (void)n_in; (void)out_size;

    fused_kernel<<<B_ROWS * SPLIT, THREADS>>>(logits, y, out);
}

// round 6
// speedup vs baseline: 1.0154x; 1.0154x over previous
#include <cuda_runtime.h>
#include <math.h>

#define C_DIM    128000
#define C_VEC    (C_DIM / 4)         // 32000 float4 per row
#define B_ROWS   2048
#define SPLIT    5
#define CHUNK_V  (C_VEC / SPLIT)     // 6400 float4 per chunk
#define THREADS  256                 // 6400 / 256 = 25 iterations exactly

// partial per (row, split): x=sum_exp, y=m1, z=m2, w=unused
__device__ float4 g_partial[B_ROWS * SPLIT];

__device__ __forceinline__ void top2_val(float& m1, float& m2, float v) {
    float t  = fminf(m1, v);
    m1 = fmaxf(m1, v);
    m2 = fmaxf(m2, t);
}

__global__ __launch_bounds__(THREADS, 8)
void phase1_kernel(const float* __restrict__ logits) {
    const int unit  = blockIdx.x;            // 0 .. B_ROWS*SPLIT-1
    const int row   = unit / SPLIT;
    const int split = unit - row * SPLIT;

    const float4* __restrict__ p =
        reinterpret_cast<const float4*>(logits + (size_t)row * C_DIM)
        + split * CHUNK_V;

    const int tid = threadIdx.x;

    float sum = 0.0f;
    float m1 = -INFINITY, m2 = -INFINITY;

    #pragma unroll 5
    for (int j = tid; j < CHUNK_V; j += THREADS) {
        float4 v = p[j];
        sum += __expf(v.x);
        sum += __expf(v.y);
        sum += __expf(v.z);
        sum += __expf(v.w);
        top2_val(m1, m2, v.x);
        top2_val(m1, m2, v.y);
        top2_val(m1, m2, v.z);
        top2_val(m1, m2, v.w);
    }

    // ---- warp reduction ----
    const unsigned FULL = 0xFFFFFFFFu;
    #pragma unroll
    for (int off = 16; off > 0; off >>= 1) {
        sum += __shfl_xor_sync(FULL, sum, off);
        float om1 = __shfl_xor_sync(FULL, m1, off);
        float om2 = __shfl_xor_sync(FULL, m2, off);
        float nm1 = fmaxf(m1, om1);
        m2 = fmaxf(fminf(m1, om1), fmaxf(m2, om2));
        m1 = nm1;
    }

    // ---- cross-warp reduction ----
    __shared__ float s_sum[THREADS / 32];
    __shared__ float s_m1[THREADS / 32];
    __shared__ float s_m2[THREADS / 32];

    const int wid = tid >> 5;
    const int lid = tid & 31;
    if (lid == 0) { s_sum[wid] = sum; s_m1[wid] = m1; s_m2[wid] = m2; }
    __syncthreads();

    if (wid == 0) {
        const int nw = THREADS / 32;
        float fsum = (lid < nw) ? s_sum[lid] : 0.0f;
        float fm1  = (lid < nw) ? s_m1[lid]  : -INFINITY;
        float fm2  = (lid < nw) ? s_m2[lid]  : -INFINITY;

        #pragma unroll
        for (int off = nw / 2; off > 0; off >>= 1) {
            fsum += __shfl_xor_sync(FULL, fsum, off);
            float om1 = __shfl_xor_sync(FULL, fm1, off);
            float om2 = __shfl_xor_sync(FULL, fm2, off);
            float nm1 = fmaxf(fm1, om1);
            fm2 = fmaxf(fminf(fm1, om1), fmaxf(fm2, om2));
            fm1 = nm1;
        }

        if (lid == 0) {
            g_partial[unit] = make_float4(fsum, fm1, fm2, 0.0f);
        }
    }
}

// One warp per row: partial loads spread across lanes (parallel), label
// gather chased concurrently by lane 0; everything overlaps across 2048 warps.
__global__ __launch_bounds__(256)
void phase2_kernel(const float* __restrict__ logits,
                   const int* __restrict__ y,
                   float* __restrict__ out) {
    const int tid  = blockIdx.x * blockDim.x + threadIdx.x;
    const int row  = tid >> 5;                // one warp per row
    const int lid  = tid & 31;
    if (row >= B_ROWS) return;

    // label gather: independent of partials, overlaps with them
    float vy = 0.0f;
    if (lid == 0) {
        int yv = y[row];
        if (yv < 0)      yv = 0;
        if (yv >= C_DIM) yv = C_DIM - 1;
        vy = __ldg(logits + (size_t)row * C_DIM + (size_t)yv);
    }

    float sum = 0.0f;
    float m1 = -INFINITY, m2 = -INFINITY;
    if (lid < SPLIT) {
        float4 v = g_partial[row * SPLIT + lid];
        sum = v.x; m1 = v.y; m2 = v.z;
    }

    const unsigned FULL = 0xFFFFFFFFu;
    #pragma unroll
    for (int off = 16; off > 0; off >>= 1) {
        sum += __shfl_xor_sync(FULL, sum, off);
        float om1 = __shfl_xor_sync(FULL, m1, off);
        float om2 = __shfl_xor_sync(FULL, m2, off);
        float nm1 = fmaxf(m1, om1);
        m2 = fmaxf(fminf(m1, om1), fmaxf(m2, om2));
        m1 = nm1;
    }

    if (lid == 0) {
        // y is argmax  <=>  logits[row][y] == global max (distinct values)
        const float first = (vy == m1) ? m2 : m1;
        out[row] = first - logf(sum - first);
    }
}

extern "C" void kernel_launch(void* const* d_in, const int* in_sizes, int n_in,
                              void* d_out, int out_size) {
    const float* logits = (const float*)d_in[0];
    const int*   y      = (const int*)d_in[1];
    float*       out    = (float*)d_out;
    (void)in_sizes; (void)n_in; (void)out_size;

    phase1_kernel<<<B_ROWS * SPLIT, THREADS>>>(logits);
    phase2_kernel<<<(B_ROWS * 32) / 256, 256>>>(logits, y, out);
}

// round 7
// speedup vs baseline: 1.0186x; 1.0032x over previous
#include <cuda_runtime.h>
#include <math.h>

#define C_DIM    128000
#define C_VEC    (C_DIM / 4)         // 32000 float4 per row
#define B_ROWS   2048
#define SPLIT    5
#define CHUNK_V  (C_VEC / SPLIT)     // 6400 float4 per chunk
#define THREADS  256                 // 6400 / 256 = 25 iterations exactly

// partial per (row, split): x=sum_exp, y=m1, z=m2, w=unused
__device__ float4 g_partial[B_ROWS * SPLIT];
// per-row arrival counter (zero-init at load; reset to 0 by the finishing
// block each call -> deterministic across graph replays)
__device__ unsigned int g_count[B_ROWS];

__device__ __forceinline__ void top2_val(float& m1, float& m2, float v) {
    float t  = fminf(m1, v);
    m1 = fmaxf(m1, v);
    m2 = fmaxf(m2, t);
}

__global__ __launch_bounds__(THREADS, 8)
void fused_kernel(const float* __restrict__ logits,
                  const int* __restrict__ y,
                  float* __restrict__ out) {
    const int unit  = blockIdx.x;            // 0 .. B_ROWS*SPLIT-1
    const int row   = unit / SPLIT;
    const int split = unit - row * SPLIT;

    const float4* __restrict__ p =
        reinterpret_cast<const float4*>(logits + (size_t)row * C_DIM)
        + split * CHUNK_V;

    const int tid = threadIdx.x;

    float sum = 0.0f;
    float m1 = -INFINITY, m2 = -INFINITY;

    #pragma unroll 5
    for (int j = tid; j < CHUNK_V; j += THREADS) {
        float4 v = p[j];
        sum += __expf(v.x);
        sum += __expf(v.y);
        sum += __expf(v.z);
        sum += __expf(v.w);
        top2_val(m1, m2, v.x);
        top2_val(m1, m2, v.y);
        top2_val(m1, m2, v.z);
        top2_val(m1, m2, v.w);
    }

    // ---- warp reduction ----
    const unsigned FULL = 0xFFFFFFFFu;
    #pragma unroll
    for (int off = 16; off > 0; off >>= 1) {
        sum += __shfl_xor_sync(FULL, sum, off);
        float om1 = __shfl_xor_sync(FULL, m1, off);
        float om2 = __shfl_xor_sync(FULL, m2, off);
        float nm1 = fmaxf(m1, om1);
        m2 = fmaxf(fminf(m1, om1), fmaxf(m2, om2));
        m1 = nm1;
    }

    // ---- cross-warp reduction ----
    __shared__ float s_sum[THREADS / 32];
    __shared__ float s_m1[THREADS / 32];
    __shared__ float s_m2[THREADS / 32];
    __shared__ unsigned int s_last;

    const int wid = tid >> 5;
    const int lid = tid & 31;
    if (lid == 0) { s_sum[wid] = sum; s_m1[wid] = m1; s_m2[wid] = m2; }
    __syncthreads();

    if (wid == 0) {
        const int nw = THREADS / 32;
        float fsum = (lid < nw) ? s_sum[lid] : 0.0f;
        float fm1  = (lid < nw) ? s_m1[lid]  : -INFINITY;
        float fm2  = (lid < nw) ? s_m2[lid]  : -INFINITY;

        #pragma unroll
        for (int off = nw / 2; off > 0; off >>= 1) {
            fsum += __shfl_xor_sync(FULL, fsum, off);
            float om1 = __shfl_xor_sync(FULL, fm1, off);
            float om2 = __shfl_xor_sync(FULL, fm2, off);
            float nm1 = fmaxf(fm1, om1);
            fm2 = fmaxf(fminf(fm1, om1), fmaxf(fm2, om2));
            fm1 = nm1;
        }

        if (lid == 0) {
            // publish this chunk's partial (plain store; ordered by the
            // release half of the acq_rel atomic below -- same thread)
            g_partial[unit] = make_float4(fsum, fm1, fm2, 0.0f);
            unsigned int prev;
            asm volatile("atom.acq_rel.gpu.global.add.u32 %0, [%1], %2;"
                         : "=r"(prev)
                         : "l"(&g_count[row]), "r"(1u)
                         : "memory");
            s_last = (prev == SPLIT - 1) ? 1u : 0u;
        }
    }
    __syncthreads();

    // ---- finalize: last-arriving block for this row, warp 0 only ----
    if (s_last && wid == 0) {
        // issue the label gather FIRST so its DRAM latency hides under the
        // partial loads + shfl merge below
        float vy = 0.0f;
        if (lid == 0) {
            int yv = y[row];
            if (yv < 0)      yv = 0;
            if (yv >= C_DIM) yv = C_DIM - 1;
            vy = __ldg(logits + (size_t)row * C_DIM + (size_t)yv);
        }

        float tsum = 0.0f;
        float tm1 = -INFINITY, tm2 = -INFINITY;
        if (lid < SPLIT) {
            float4 v = g_partial[row * SPLIT + lid];
            tsum = v.x; tm1 = v.y; tm2 = v.z;
        }
        #pragma unroll
        for (int off = 4; off > 0; off >>= 1) {
            tsum += __shfl_xor_sync(FULL, tsum, off);
            float om1 = __shfl_xor_sync(FULL, tm1, off);
            float om2 = __shfl_xor_sync(FULL, tm2, off);
            float nm1 = fmaxf(tm1, om1);
            tm2 = fmaxf(fminf(tm1, om1), fmaxf(tm2, om2));
            tm1 = nm1;
        }

        if (lid == 0) {
            // y is argmax  <=>  logits[row][y] == global max (distinct values)
            const float first = (vy == tm1) ? tm2 : tm1;
            out[row] = first - logf(tsum - first);

            // reset counter for the next (graph-replayed) call
            g_count[row] = 0u;
        }
    }
}

extern "C" void kernel_launch(void* const* d_in, const int* in_sizes, int n_in,
                              void* d_out, int out_size) {
    const float* logits = (const float*)d_in[0];
    const int*   y      = (const int*)d_in[1];
    float*       out    = (float*)d_out;
    (void)in_sizes; (void)n_in; (void)out_size;

    fused_kernel<<<B_ROWS * SPLIT, THREADS>>>(logits, y, out);
}